// round 5
// baseline (speedup 1.0000x reference)
#include <cuda_runtime.h>

// TwoRobots Euler step, affine form. R5: 256-bit (v4.b64) loads/stores with
// L2::evict_last — the only vector width ptxas accepts that modifier on for
// sm_103. Working set (112 MB) < L2 (126 MB): evict_last pins it across graph
// replays so DRAM traffic collapses toward the LTS cap.

#define HSTEP 0.05f
#define KS    2.0f
#define CD    2.0f

struct f8 { float v[8]; };

__device__ __forceinline__ f8 ldg_el(const float* p) {
    unsigned long long r0, r1, r2, r3;
    asm volatile("ld.global.L2::evict_last.v4.b64 {%0,%1,%2,%3}, [%4];"
                 : "=l"(r0), "=l"(r1), "=l"(r2), "=l"(r3)
                 : "l"(p));
    f8 o;
    o.v[0] = __uint_as_float((unsigned)r0); o.v[1] = __uint_as_float((unsigned)(r0 >> 32));
    o.v[2] = __uint_as_float((unsigned)r1); o.v[3] = __uint_as_float((unsigned)(r1 >> 32));
    o.v[4] = __uint_as_float((unsigned)r2); o.v[5] = __uint_as_float((unsigned)(r2 >> 32));
    o.v[6] = __uint_as_float((unsigned)r3); o.v[7] = __uint_as_float((unsigned)(r3 >> 32));
    return o;
}

__device__ __forceinline__ void stg_el(float* p, const f8& a) {
    unsigned long long r0 = (unsigned long long)__float_as_uint(a.v[0]) |
                            ((unsigned long long)__float_as_uint(a.v[1]) << 32);
    unsigned long long r1 = (unsigned long long)__float_as_uint(a.v[2]) |
                            ((unsigned long long)__float_as_uint(a.v[3]) << 32);
    unsigned long long r2 = (unsigned long long)__float_as_uint(a.v[4]) |
                            ((unsigned long long)__float_as_uint(a.v[5]) << 32);
    unsigned long long r3 = (unsigned long long)__float_as_uint(a.v[6]) |
                            ((unsigned long long)__float_as_uint(a.v[7]) << 32);
    asm volatile("st.global.L2::evict_last.v4.b64 [%0], {%1,%2,%3,%4};"
                 :: "l"(p), "l"(r0), "l"(r1), "l"(r2), "l"(r3)
                 : "memory");
}

__global__ __launch_bounds__(256)
void tworobots_pair8(const float* __restrict__ x,
                     const float* __restrict__ u,
                     const float* __restrict__ w,
                     const float* __restrict__ xbar,
                     float* __restrict__ out,
                     int B, int n8)
{
    const int i = blockIdx.x * blockDim.x + threadIdx.x;
    if (i >= n8) return;
    const int col = i * 8;

    const int pair = blockIdx.y;                 // 0..3
    const int pr   = pair + ((pair >> 1) << 1);  // 0,1,4,5
    const int vr   = pr + 2;                     // 2,3,6,7

    const float xb = __ldg(&xbar[pr]);

    // 5 independent 32B loads, front-batched -> 160B in flight per thread.
    const f8 xp = ldg_el(x + (size_t)pr   * B + col);
    const f8 xv = ldg_el(x + (size_t)vr   * B + col);
    const f8 uu = ldg_el(u + (size_t)pair * B + col);
    const f8 wp = ldg_el(w + (size_t)pr   * B + col);
    const f8 wv = ldg_el(w + (size_t)vr   * B + col);

    f8 op, ov;
#pragma unroll
    for (int k = 0; k < 8; k++) {
        float fg = fmaf(-KS, (xp.v[k] - xb), -CD * xv.v[k]);
        op.v[k] = fmaf(HSTEP, xv.v[k], xp.v[k]) + wp.v[k];
        ov.v[k] = fmaf(HSTEP, (fg + uu.v[k]), xv.v[k]) + wv.v[k];
    }

    stg_el(out + (size_t)pr * B + col, op);
    stg_el(out + (size_t)vr * B + col, ov);
}

// Fallback for B % 8 != 0 — R2's proven float4/scalar-free path.
__global__ __launch_bounds__(256)
void tworobots_pair_scalar(const float* __restrict__ x,
                           const float* __restrict__ u,
                           const float* __restrict__ w,
                           const float* __restrict__ xbar,
                           float* __restrict__ out,
                           int B)
{
    const int i = blockIdx.x * blockDim.x + threadIdx.x;
    if (i >= B) return;

    const int pair = blockIdx.y;
    const int pr   = pair + ((pair >> 1) << 1);
    const int vr   = pr + 2;

    const float xb = __ldg(&xbar[pr]);

    const float xp = x[(size_t)pr   * B + i];
    const float xv = x[(size_t)vr   * B + i];
    const float uu = u[(size_t)pair * B + i];
    const float wp = w[(size_t)pr   * B + i];
    const float wv = w[(size_t)vr   * B + i];

    float fg = fmaf(-KS, (xp - xb), -CD * xv);
    out[(size_t)pr * B + i] = fmaf(HSTEP, xv, xp) + wp;
    out[(size_t)vr * B + i] = fmaf(HSTEP, (fg + uu), xv) + wv;
}

extern "C" void kernel_launch(void* const* d_in, const int* in_sizes, int n_in,
                              void* d_out, int out_size)
{
    const float* x    = (const float*)d_in[0];   // [8, B]
    const float* u    = (const float*)d_in[1];   // [4, B]
    const float* w    = (const float*)d_in[2];   // [8, B]
    const float* xbar = (const float*)d_in[3];   // [8]
    float* out = (float*)d_out;                  // [8, B]

    const int B = in_sizes[0] / 8;
    const int threads = 256;

    if ((B & 7) == 0) {
        const int n8 = B / 8;
        dim3 grid((n8 + threads - 1) / threads, 4);
        tworobots_pair8<<<grid, threads>>>(x, u, w, xbar, out, B, n8);
    } else {
        dim3 grid((B + threads - 1) / threads, 4);
        tworobots_pair_scalar<<<grid, threads>>>(x, u, w, xbar, out, B);
    }
}

// round 6
// speedup vs baseline: 1.2937x; 1.2937x over previous
#include <cuda_runtime.h>

// TwoRobots Euler step, affine form. R6: R2's proven structure (float4, flat
// grid, one item/thread, 32 regs) + asymmetric L2 policy via createpolicy:
//   loads  -> evict_last  (pin the 80 MB input set across graph replays)
//   stores -> evict_first (32 MB write-once output streams out w/o evicting inputs)

#define HSTEP 0.05f
#define KS    2.0f
#define CD    2.0f

__device__ __forceinline__ unsigned long long mkpolicy_evict_last() {
    unsigned long long p;
    asm("createpolicy.fractional.L2::evict_last.b64 %0, 1.0;" : "=l"(p));
    return p;
}

__device__ __forceinline__ unsigned long long mkpolicy_evict_first() {
    unsigned long long p;
    asm("createpolicy.fractional.L2::evict_first.b64 %0, 1.0;" : "=l"(p));
    return p;
}

__device__ __forceinline__ float4 ldg_hint(const float4* p, unsigned long long pol) {
    float4 v;
    asm volatile("ld.global.L2::cache_hint.v4.f32 {%0,%1,%2,%3}, [%4], %5;"
                 : "=f"(v.x), "=f"(v.y), "=f"(v.z), "=f"(v.w)
                 : "l"(p), "l"(pol));
    return v;
}

__device__ __forceinline__ void stg_hint(float4* p, float4 v, unsigned long long pol) {
    asm volatile("st.global.L2::cache_hint.v4.f32 [%0], {%1,%2,%3,%4}, %5;"
                 :: "l"(p), "f"(v.x), "f"(v.y), "f"(v.z), "f"(v.w), "l"(pol)
                 : "memory");
}

__global__ __launch_bounds__(256)
void tworobots_pair(const float4* __restrict__ x,
                    const float4* __restrict__ u,
                    const float4* __restrict__ w,
                    const float*  __restrict__ xbar,
                    float4* __restrict__ out,
                    int n4)
{
    const int i = blockIdx.x * blockDim.x + threadIdx.x;
    if (i >= n4) return;

    const int pair = blockIdx.y;                 // 0..3
    const int pr   = pair + ((pair >> 1) << 1);  // 0,1,4,5
    const int vr   = pr + 2;                     // 2,3,6,7

    const float xb = __ldg(&xbar[pr]);

    const unsigned long long polL = mkpolicy_evict_last();
    const unsigned long long polS = mkpolicy_evict_first();

    // 5 independent loads, front-batched -> MLP=5 per warp.
    const float4 xp = ldg_hint(x + (size_t)pr   * n4 + i, polL);
    const float4 xv = ldg_hint(x + (size_t)vr   * n4 + i, polL);
    const float4 uu = ldg_hint(u + (size_t)pair * n4 + i, polL);
    const float4 wp = ldg_hint(w + (size_t)pr   * n4 + i, polL);
    const float4 wv = ldg_hint(w + (size_t)vr   * n4 + i, polL);

    float4 op, ov;
#define LANE(c)                                                  \
    {                                                            \
        float fg = fmaf(-KS, (xp.c - xb), -CD * xv.c);           \
        op.c = fmaf(HSTEP, xv.c, xp.c) + wp.c;                   \
        ov.c = fmaf(HSTEP, (fg + uu.c), xv.c) + wv.c;            \
    }
    LANE(x) LANE(y) LANE(z) LANE(w)
#undef LANE

    stg_hint(out + (size_t)pr * n4 + i, op, polS);
    stg_hint(out + (size_t)vr * n4 + i, ov, polS);
}

// Scalar fallback (B % 4 != 0) — plain accesses, same math.
__global__ __launch_bounds__(256)
void tworobots_pair_scalar(const float* __restrict__ x,
                           const float* __restrict__ u,
                           const float* __restrict__ w,
                           const float* __restrict__ xbar,
                           float* __restrict__ out,
                           int B)
{
    const int i = blockIdx.x * blockDim.x + threadIdx.x;
    if (i >= B) return;

    const int pair = blockIdx.y;
    const int pr   = pair + ((pair >> 1) << 1);
    const int vr   = pr + 2;

    const float xb = __ldg(&xbar[pr]);

    const float xp = x[(size_t)pr   * B + i];
    const float xv = x[(size_t)vr   * B + i];
    const float uu = u[(size_t)pair * B + i];
    const float wp = w[(size_t)pr   * B + i];
    const float wv = w[(size_t)vr   * B + i];

    float fg = fmaf(-KS, (xp - xb), -CD * xv);
    out[(size_t)pr * B + i] = fmaf(HSTEP, xv, xp) + wp;
    out[(size_t)vr * B + i] = fmaf(HSTEP, (fg + uu), xv) + wv;
}

extern "C" void kernel_launch(void* const* d_in, const int* in_sizes, int n_in,
                              void* d_out, int out_size)
{
    const float* x    = (const float*)d_in[0];   // [8, B]
    const float* u    = (const float*)d_in[1];   // [4, B]
    const float* w    = (const float*)d_in[2];   // [8, B]
    const float* xbar = (const float*)d_in[3];   // [8]
    float* out = (float*)d_out;                  // [8, B]

    const int B = in_sizes[0] / 8;
    const int threads = 256;

    if ((B & 3) == 0) {
        const int n4 = B / 4;
        dim3 grid((n4 + threads - 1) / threads, 4);
        tworobots_pair<<<grid, threads>>>((const float4*)x, (const float4*)u,
                                          (const float4*)w, xbar,
                                          (float4*)out, n4);
    } else {
        dim3 grid((B + threads - 1) / threads, 4);
        tworobots_pair_scalar<<<grid, threads>>>(x, u, w, xbar, out, B);
    }
}